// round 1
// baseline (speedup 1.0000x reference)
#include <cuda_runtime.h>
#include <cuda_bf16.h>

#define D 128
#define K2 256
#define MAXN 50016
#define MAXDEG 96
#define TILE_R 64
#define XPITCH 66
#define GEMM_THREADS 256

// Scratch (static __device__ arrays: allowed; runtime allocation is not)
__device__ int   g_cnt[MAXN];               // in-degree / cursor
__device__ int   g_esrc[MAXN * MAXDEG];     // padded in-edge source lists (~19.2 MB)
__device__ float g_h[MAXN * D];             // normalized neighbor means (~25.6 MB)

// ---------------- Kernel 1: zero degree counters ----------------
__global__ void k_zero(int N) {
    int i = blockIdx.x * blockDim.x + threadIdx.x;
    if (i < N) g_cnt[i] = 0;
}

// ---------------- Kernel 2: build padded in-edge lists ----------------
__global__ void k_scatter(const int* __restrict__ src, const int* __restrict__ dst, int E) {
    int e = blockIdx.x * blockDim.x + threadIdx.x;
    if (e < E) {
        int v = dst[e];
        int pos = atomicAdd(&g_cnt[v], 1);
        if (pos < MAXDEG) g_esrc[v * MAXDEG + pos] = src[e];
    }
}

// ---------------- Kernel 3: pull-mode mean aggregation ----------------
// One warp per destination node; lane l owns feature elements [4l, 4l+4).
// Each edge read is one contiguous 512B row (32 lanes x float4) -> L2-resident.
__global__ void k_agg(const float* __restrict__ feat, int N) {
    int w    = (blockIdx.x * blockDim.x + threadIdx.x) >> 5;
    int lane = threadIdx.x & 31;
    if (w >= N) return;
    int d = g_cnt[w];
    if (d > MAXDEG) d = MAXDEG;
    const int* lst = g_esrc + (size_t)w * MAXDEG;
    const float4* f4 = (const float4*)feat;

    float4 acc = make_float4(0.f, 0.f, 0.f, 0.f);
    int i = 0;
    for (; i + 2 <= d; i += 2) {               // 2 edges in flight for MLP
        int s0 = __ldg(&lst[i]);
        int s1 = __ldg(&lst[i + 1]);
        float4 a = __ldg(&f4[(size_t)s0 * 32 + lane]);
        float4 b = __ldg(&f4[(size_t)s1 * 32 + lane]);
        acc.x += a.x; acc.y += a.y; acc.z += a.z; acc.w += a.w;
        acc.x += b.x; acc.y += b.y; acc.z += b.z; acc.w += b.w;
    }
    if (i < d) {
        int s0 = __ldg(&lst[i]);
        float4 a = __ldg(&f4[(size_t)s0 * 32 + lane]);
        acc.x += a.x; acc.y += a.y; acc.z += a.z; acc.w += a.w;
    }
    float inv = 1.0f / (float)(d > 0 ? d : 1);
    float4 r = make_float4(acc.x * inv, acc.y * inv, acc.z * inv, acc.w * inv);
    ((float4*)g_h)[(size_t)w * 32 + lane] = r;
}

// ---------------- Kernel 4: fused GEMM  out = [feat|h] @ [Wself;Wneigh] + b ----
__device__ __forceinline__ unsigned long long pack2f(float x, float y) {
    unsigned long long r;
    asm("mov.b64 %0, {%1, %2};" : "=l"(r) : "f"(x), "f"(y));
    return r;
}
__device__ __forceinline__ void fma2(unsigned long long& d_,
                                     unsigned long long a, unsigned long long b) {
    // packed dual-fp32 FMA (Blackwell f32x2 pipe)
    asm("fma.rn.f32x2 %0, %1, %2, %0;" : "+l"(d_) : "l"(a), "l"(b));
}

__global__ void __launch_bounds__(GEMM_THREADS, 1)
k_gemm(const float* __restrict__ feat,
       const float* __restrict__ Wself,
       const float* __restrict__ Wneigh,
       const float* __restrict__ bias,
       float* __restrict__ out, int N) {
    extern __shared__ float sm[];
    float* W2s = sm;                 // [256][128]  (128 KB)
    float* Xs  = sm + K2 * D;        // [256][XPITCH] transposed X tile (~66 KB)

    const int t  = threadIdx.x;
    const int cb = t & 31;           // column base lane
    const int r0 = (t >> 5) * 8;     // 8-row group per warp-slot

    // stage both weight matrices into SMEM (row-major [k][j])
    for (int idx = t; idx < D * D; idx += GEMM_THREADS) {
        W2s[idx]          = Wself[idx];
        W2s[D * D + idx]  = Wneigh[idx];
    }
    float bj[4];
#pragma unroll
    for (int cc = 0; cc < 4; ++cc) bj[cc] = bias[cb + 32 * cc];

    const int base = blockIdx.x * TILE_R;

    // load X tile transposed: Xs[k][r] = feat ; Xs[128+k][r] = h_neigh (already normalized)
    for (int idx = t; idx < TILE_R * D; idx += GEMM_THREADS) {
        int r = idx >> 7;
        int k = idx & 127;
        int n = base + r;
        float fv = 0.f, hv = 0.f;
        if (n < N) {
            fv = feat[(size_t)n * D + k];
            hv = g_h[(size_t)n * D + k];
        }
        Xs[k * XPITCH + r]         = fv;
        Xs[(128 + k) * XPITCH + r] = hv;
    }
    __syncthreads();

    // register tile: 8 rows (4 f32x2 pairs) x 4 cols
    unsigned long long acc[4][4];
#pragma unroll
    for (int cc = 0; cc < 4; ++cc)
#pragma unroll
        for (int p = 0; p < 4; ++p) acc[cc][p] = pack2f(bj[cc], bj[cc]);

#pragma unroll 4
    for (int k = 0; k < K2; ++k) {
        const float* xr = Xs + k * XPITCH + r0;        // broadcast across warp
        unsigned long long a[4];
#pragma unroll
        for (int p = 0; p < 4; ++p)
            a[p] = *reinterpret_cast<const unsigned long long*>(xr + 2 * p);
        const float* wr = W2s + k * D + cb;            // conflict-free (j consecutive)
#pragma unroll
        for (int cc = 0; cc < 4; ++cc) {
            float w = wr[cc * 32];
            unsigned long long ww = pack2f(w, w);
#pragma unroll
            for (int p = 0; p < 4; ++p) fma2(acc[cc][p], a[p], ww);
        }
    }

    // store (coalesced across cb)
#pragma unroll
    for (int cc = 0; cc < 4; ++cc) {
        int j = cb + 32 * cc;
#pragma unroll
        for (int p = 0; p < 4; ++p) {
            int n = base + r0 + 2 * p;
            union { unsigned long long u; float2 f; } cv;
            cv.u = acc[cc][p];
            if (n < N)     out[(size_t)n * D + j]       = cv.f.x;
            if (n + 1 < N) out[(size_t)(n + 1) * D + j] = cv.f.y;
        }
    }
}

// ---------------- launch ----------------
extern "C" void kernel_launch(void* const* d_in, const int* in_sizes, int n_in,
                              void* d_out, int out_size) {
    const float* feat = (const float*)d_in[0];
    const int*   src  = (const int*)d_in[1];
    const int*   dst  = (const int*)d_in[2];
    const float* Ws   = (const float*)d_in[3];
    const float* Wn   = (const float*)d_in[4];
    const float* b    = (const float*)d_in[5];
    float*       out  = (float*)d_out;

    const int N = in_sizes[0] / D;
    const int E = in_sizes[1];

    k_zero<<<(N + 255) / 256, 256>>>(N);
    k_scatter<<<(E + 255) / 256, 256>>>(src, dst, E);
    k_agg<<<(N + 7) / 8, 256>>>(feat, N);   // 8 warps/block, 1 warp/node

    const int smem = (K2 * D + K2 * XPITCH) * (int)sizeof(float);  // 198656 B
    cudaFuncSetAttribute(k_gemm, cudaFuncAttributeMaxDynamicSharedMemorySize, smem);
    k_gemm<<<(N + TILE_R - 1) / TILE_R, GEMM_THREADS, smem>>>(feat, Ws, Wn, b, out, N);
}

// round 3
// speedup vs baseline: 1.8237x; 1.8237x over previous
#include <cuda_runtime.h>
#include <cuda_bf16.h>
#include <cstdint>

#define D 128
#define K2 256
#define NPAD 50048
#define MAXDEG 96

// ---------------- static device scratch ----------------
__device__ int   g_cnt[NPAD];
__device__ int   g_esrc[NPAD * MAXDEG];
__device__ __nv_bfloat16 g_Xhi[(size_t)NPAD * K2];   // [n][256]: cols 0-127 feat, 128-255 h
__device__ __nv_bfloat16 g_Xlo[(size_t)NPAD * K2];
__device__ __nv_bfloat16 g_Wth[D * K2];              // B operand [j][k] hi  (W2 transposed)
__device__ __nv_bfloat16 g_Wtl[D * K2];              // lo

#define SWZ(o) ((o) ^ (((o) >> 3) & 0x70))

// ---------------- helpers ----------------
__device__ __forceinline__ void hilo(float x, __nv_bfloat16& h, __nv_bfloat16& l) {
    h = __float2bfloat16_rn(x);
    l = __float2bfloat16_rn(x - __bfloat162float(h));
}
__device__ __forceinline__ uint32_t smem_u32(const void* p) {
    uint32_t a;
    asm("{ .reg .u64 t; cvta.to.shared.u64 t, %1; cvt.u32.u64 %0, t; }" : "=r"(a) : "l"(p));
    return a;
}
#define LDM_X4(r, a) \
    asm volatile("ldmatrix.sync.aligned.m8n8.x4.shared.b16 {%0,%1,%2,%3}, [%4];" \
        : "=r"((r)[0]), "=r"((r)[1]), "=r"((r)[2]), "=r"((r)[3]) : "r"(a))
#define MMA16816(c, a, b0, b1) \
    asm volatile("mma.sync.aligned.m16n8k16.row.col.f32.bf16.bf16.f32 " \
        "{%0,%1,%2,%3},{%4,%5,%6,%7},{%8,%9},{%0,%1,%2,%3};" \
        : "+f"((c)[0]), "+f"((c)[1]), "+f"((c)[2]), "+f"((c)[3]) \
        : "r"((a)[0]), "r"((a)[1]), "r"((a)[2]), "r"((a)[3]), "r"(b0), "r"(b1))
#define CP16(s, g) \
    asm volatile("cp.async.cg.shared.global [%0], [%1], 16;" :: "r"(s), "l"(g))
#define CP_COMMIT()  asm volatile("cp.async.commit_group;" ::: "memory")
#define CP_WAIT(n)   asm volatile("cp.async.wait_group %0;" :: "n"(n) : "memory")

// ---------------- K1: zero counters ----------------
__global__ void k_zero(int N) {
    int i = blockIdx.x * blockDim.x + threadIdx.x;
    if (i < N) g_cnt[i] = 0;
}

// ---------------- K2: features -> bf16 hi/lo (cols 0..127) ----------------
__global__ void k_convx(const float* __restrict__ feat, int N) {
    int i = blockIdx.x * blockDim.x + threadIdx.x;
    if (i >= N * 32) return;
    int n = i >> 5, q = i & 31;
    float4 v = ((const float4*)feat)[i];
    __nv_bfloat16 h0, h1, h2, h3, l0, l1, l2, l3;
    hilo(v.x, h0, l0); hilo(v.y, h1, l1); hilo(v.z, h2, l2); hilo(v.w, h3, l3);
    union { __nv_bfloat162 b[2]; uint2 u; } ph, pl;
    ph.b[0] = __nv_bfloat162(h0, h1); ph.b[1] = __nv_bfloat162(h2, h3);
    pl.b[0] = __nv_bfloat162(l0, l1); pl.b[1] = __nv_bfloat162(l2, l3);
    size_t off = (size_t)n * K2 + q * 4;
    *(uint2*)(g_Xhi + off) = ph.u;
    *(uint2*)(g_Xlo + off) = pl.u;
}

// ---------------- K3: W2 transposed [j][k] -> bf16 hi/lo ----------------
__global__ void k_convw(const float* __restrict__ Ws, const float* __restrict__ Wn) {
    int i = blockIdx.x * blockDim.x + threadIdx.x;
    if (i >= D * K2) return;
    int j = i >> 8, k = i & 255;
    float w = (k < D) ? Ws[k * D + j] : Wn[(k - D) * D + j];
    __nv_bfloat16 h, l;
    hilo(w, h, l);
    g_Wth[j * K2 + k] = h;
    g_Wtl[j * K2 + k] = l;
}

// ---------------- K4: padded in-edge lists ----------------
__global__ void k_scatter(const int* __restrict__ src, const int* __restrict__ dst, int E) {
    int e = blockIdx.x * blockDim.x + threadIdx.x;
    if (e < E) {
        int v = dst[e];
        int pos = atomicAdd(&g_cnt[v], 1);
        if (pos < MAXDEG) g_esrc[v * MAXDEG + pos] = src[e];
    }
}

// ---------------- K5: pull-mode mean aggregation (bf16 gather, fp32 accum) ----
__global__ void k_agg(int N) {
    int w    = (blockIdx.x * blockDim.x + threadIdx.x) >> 5;
    int lane = threadIdx.x & 31;
    if (w >= N) return;
    int d = g_cnt[w];
    if (d > MAXDEG) d = MAXDEG;
    const int* lst = g_esrc + (size_t)w * MAXDEG;

    float a0 = 0.f, a1 = 0.f, a2 = 0.f, a3 = 0.f;
    int i = 0;
    for (; i + 2 <= d; i += 2) {
        int s0 = __ldg(&lst[i]);
        int s1 = __ldg(&lst[i + 1]);
        union { uint2 u; __nv_bfloat162 b[2]; } c0, c1;
        c0.u = *(const uint2*)(g_Xhi + (size_t)s0 * K2 + lane * 4);
        c1.u = *(const uint2*)(g_Xhi + (size_t)s1 * K2 + lane * 4);
        float2 f;
        f = __bfloat1622float2(c0.b[0]); a0 += f.x; a1 += f.y;
        f = __bfloat1622float2(c0.b[1]); a2 += f.x; a3 += f.y;
        f = __bfloat1622float2(c1.b[0]); a0 += f.x; a1 += f.y;
        f = __bfloat1622float2(c1.b[1]); a2 += f.x; a3 += f.y;
    }
    if (i < d) {
        int s0 = __ldg(&lst[i]);
        union { uint2 u; __nv_bfloat162 b[2]; } c0;
        c0.u = *(const uint2*)(g_Xhi + (size_t)s0 * K2 + lane * 4);
        float2 f;
        f = __bfloat1622float2(c0.b[0]); a0 += f.x; a1 += f.y;
        f = __bfloat1622float2(c0.b[1]); a2 += f.x; a3 += f.y;
    }
    float inv = 1.0f / (float)(d > 0 ? d : 1);
    __nv_bfloat16 h0, h1, h2, h3, l0, l1, l2, l3;
    hilo(a0 * inv, h0, l0); hilo(a1 * inv, h1, l1);
    hilo(a2 * inv, h2, l2); hilo(a3 * inv, h3, l3);
    union { __nv_bfloat162 b[2]; uint2 u; } ph, pl;
    ph.b[0] = __nv_bfloat162(h0, h1); ph.b[1] = __nv_bfloat162(h2, h3);
    pl.b[0] = __nv_bfloat162(l0, l1); pl.b[1] = __nv_bfloat162(l2, l3);
    size_t off = (size_t)w * K2 + D + lane * 4;
    *(uint2*)(g_Xhi + off) = ph.u;
    *(uint2*)(g_Xlo + off) = pl.u;
}

// ---------------- K6: HMMA GEMM  out = X @ W2t^T + b  (bf16 hi/lo split) -----
// CTA: M=128 x N=128, K=256 in 4 chunks of 64 (row = 128B, XOR swizzle).
// Warps 4(m) x 2(n): warp tile 32 x 64.
#define CHUNK_BYTES 16384            // 128 rows x 128 B
#define BUF_BYTES   65536            // Ahi Alo Bhi Blo
#define SM_BIAS     (2 * BUF_BYTES)  // 131072
#define SM_TOTAL    (SM_BIAS + D * 4)

__global__ void __launch_bounds__(256, 1)
k_gemm(const float* __restrict__ bias, float* __restrict__ out, int N) {
    extern __shared__ char smem[];
    const uint32_t sbase = smem_u32(smem);
    const int t    = threadIdx.x;
    const int lane = t & 31;
    const int wid  = t >> 5;
    const int m0   = (wid & 3) * 32;           // warp m-origin
    const int n0w  = (wid >> 2) * 64;          // warp n-origin
    const int base = blockIdx.x * 128;

    if (t < D) ((float*)(smem + SM_BIAS))[t] = bias[t];

    // per-lane ldmatrix address components
    const int qa = lane >> 3;
    const uint32_t rowA = (lane & 7) + ((qa & 1) << 3);     // + mt*16 + m0
    const uint32_t kbA  = (qa >> 1) << 4;
    const uint32_t rowB = (lane & 7) + ((qa >> 1) << 3);    // + nb*16 + n0w
    const uint32_t kbB  = (qa & 1) << 4;

    // chunk loader: 4 sub-tiles x 1024 16B-units, 16 cp.async per thread
    auto load_chunk = [&](int c, int b) {
        uint32_t sb = sbase + b * BUF_BYTES;
        const char* gAh = (const char*)(g_Xhi + (size_t)base * K2 + c * 64);
        const char* gAl = (const char*)(g_Xlo + (size_t)base * K2 + c * 64);
        const char* gBh = (const char*)(g_Wth + c * 64);
        const char* gBl = (const char*)(g_Wtl + c * 64);
#pragma unroll
        for (int r = 0; r < 4; ++r) {
            int u   = t + 256 * r;
            int row = u >> 3, kk = u & 7;
            uint32_t so = SWZ((uint32_t)(row * 128 + kk * 16));
            size_t   go = (size_t)row * 512 + kk * 16;      // gmem row stride 512B
            CP16(sb +                 so, gAh + go);
            CP16(sb + CHUNK_BYTES +   so, gAl + go);
            CP16(sb + 2*CHUNK_BYTES + so, gBh + go);
            CP16(sb + 3*CHUNK_BYTES + so, gBl + go);
        }
        CP_COMMIT();
    };

    float acc[2][8][4];
#pragma unroll
    for (int mt = 0; mt < 2; ++mt)
#pragma unroll
        for (int nt = 0; nt < 8; ++nt)
#pragma unroll
            for (int q = 0; q < 4; ++q) acc[mt][nt][q] = 0.f;

    load_chunk(0, 0);

    for (int c = 0; c < 4; ++c) {
        if (c < 3) { load_chunk(c + 1, (c + 1) & 1); CP_WAIT(1); }
        else       { CP_WAIT(0); }
        __syncthreads();

        const uint32_t bA = sbase + (c & 1) * BUF_BYTES;
        const uint32_t bB = bA + 2 * CHUNK_BYTES;
#pragma unroll
        for (int ks = 0; ks < 4; ++ks) {
            uint32_t ah[2][4], al[2][4], bh[4][4], bl[4][4];
#pragma unroll
            for (int mt = 0; mt < 2; ++mt) {
                uint32_t off = SWZ((uint32_t)((m0 + mt * 16 + rowA) * 128 + ks * 32 + kbA));
                LDM_X4(ah[mt], bA + off);
                LDM_X4(al[mt], bA + CHUNK_BYTES + off);
            }
#pragma unroll
            for (int nb = 0; nb < 4; ++nb) {
                uint32_t off = SWZ((uint32_t)((n0w + nb * 16 + rowB) * 128 + ks * 32 + kbB));
                LDM_X4(bh[nb], bB + off);
                LDM_X4(bl[nb], bB + CHUNK_BYTES + off);
            }
#pragma unroll
            for (int mt = 0; mt < 2; ++mt)
#pragma unroll
                for (int nb = 0; nb < 4; ++nb) {
                    MMA16816(acc[mt][nb * 2],     ah[mt], bh[nb][0], bh[nb][1]);
                    MMA16816(acc[mt][nb * 2 + 1], ah[mt], bh[nb][2], bh[nb][3]);
                    MMA16816(acc[mt][nb * 2],     ah[mt], bl[nb][0], bl[nb][1]);
                    MMA16816(acc[mt][nb * 2 + 1], ah[mt], bl[nb][2], bl[nb][3]);
                    MMA16816(acc[mt][nb * 2],     al[mt], bh[nb][0], bh[nb][1]);
                    MMA16816(acc[mt][nb * 2 + 1], al[mt], bh[nb][2], bh[nb][3]);
                }
        }
        __syncthreads();
    }

    // epilogue: c0,c1 -> (row, col..col+1), c2,c3 -> (row+8, ...)
    const float* sb = (const float*)(smem + SM_BIAS);
#pragma unroll
    for (int mt = 0; mt < 2; ++mt) {
        int row = m0 + mt * 16 + (lane >> 2);
#pragma unroll
        for (int nt = 0; nt < 8; ++nt) {
            int j = n0w + nt * 8 + (lane & 3) * 2;
            float2 bb = make_float2(sb[j], sb[j + 1]);
            int n0 = base + row, n1 = n0 + 8;
            if (n0 < N) {
                float2 v = make_float2(acc[mt][nt][0] + bb.x, acc[mt][nt][1] + bb.y);
                *(float2*)(out + (size_t)n0 * D + j) = v;
            }
            if (n1 < N) {
                float2 v = make_float2(acc[mt][nt][2] + bb.x, acc[mt][nt][3] + bb.y);
                *(float2*)(out + (size_t)n1 * D + j) = v;
            }
        }
    }
}

// ---------------- launch ----------------
extern "C" void kernel_launch(void* const* d_in, const int* in_sizes, int n_in,
                              void* d_out, int out_size) {
    const float* feat = (const float*)d_in[0];
    const int*   src  = (const int*)d_in[1];
    const int*   dst  = (const int*)d_in[2];
    const float* Ws   = (const float*)d_in[3];
    const float* Wn   = (const float*)d_in[4];
    const float* b    = (const float*)d_in[5];
    float*       out  = (float*)d_out;

    const int N = in_sizes[0] / D;
    const int E = in_sizes[1];

    k_zero   <<<(N + 255) / 256, 256>>>(N);
    k_convx  <<<(N * 32 + 255) / 256, 256>>>(feat, N);
    k_convw  <<<(D * K2 + 255) / 256, 256>>>(Ws, Wn);
    k_scatter<<<(E + 255) / 256, 256>>>(src, dst, E);
    k_agg    <<<(N + 7) / 8, 256>>>(N);

    const int grid = (N + 127) / 128;
    cudaFuncSetAttribute(k_gemm, cudaFuncAttributeMaxDynamicSharedMemorySize, SM_TOTAL);
    k_gemm<<<grid, 256, SM_TOTAL>>>(b, out, N);
}

// round 4
// speedup vs baseline: 2.3386x; 1.2824x over previous
#include <cuda_runtime.h>
#include <cuda_fp16.h>
#include <cstdint>

#define D 128
#define K2 256
#define NPAD 50048
#define MAXDEG 96

// ---------------- static device scratch ----------------
__device__ int    g_cnt[NPAD];
__device__ int    g_esrc[NPAD * MAXDEG];
__device__ __half g_X[(size_t)NPAD * K2];    // [n][256]: cols 0-127 feat, 128-255 h
__device__ __half g_Wt[D * K2];              // B operand [j][k] (W2 transposed)

#define SWZ(o) ((o) ^ (((o) >> 3) & 0x70))

__device__ __forceinline__ uint32_t smem_u32(const void* p) {
    uint32_t a;
    asm("{ .reg .u64 t; cvta.to.shared.u64 t, %1; cvt.u32.u64 %0, t; }" : "=r"(a) : "l"(p));
    return a;
}
#define LDM_X4(r, a) \
    asm volatile("ldmatrix.sync.aligned.m8n8.x4.shared.b16 {%0,%1,%2,%3}, [%4];" \
        : "=r"((r)[0]), "=r"((r)[1]), "=r"((r)[2]), "=r"((r)[3]) : "r"(a))
#define MMA16816(c, a, b0, b1) \
    asm volatile("mma.sync.aligned.m16n8k16.row.col.f32.f16.f16.f32 " \
        "{%0,%1,%2,%3},{%4,%5,%6,%7},{%8,%9},{%0,%1,%2,%3};" \
        : "+f"((c)[0]), "+f"((c)[1]), "+f"((c)[2]), "+f"((c)[3]) \
        : "r"((a)[0]), "r"((a)[1]), "r"((a)[2]), "r"((a)[3]), "r"(b0), "r"(b1))
#define CP16(s, g) \
    asm volatile("cp.async.cg.shared.global [%0], [%1], 16;" :: "r"(s), "l"(g))
#define CP_COMMIT()  asm volatile("cp.async.commit_group;" ::: "memory")
#define CP_WAIT(n)   asm volatile("cp.async.wait_group %0;" :: "n"(n) : "memory")

// ---------------- K1: features -> fp16, also zero g_cnt ----------------
__global__ void k_convx(const float* __restrict__ feat, int N) {
    int i = blockIdx.x * blockDim.x + threadIdx.x;
    if (i < N) g_cnt[i] = 0;
    if (i >= N * 32) return;
    int n = i >> 5, q = i & 31;
    float4 v = ((const float4*)feat)[i];
    union { __half2 h[2]; uint2 u; } p;
    p.h[0] = __floats2half2_rn(v.x, v.y);
    p.h[1] = __floats2half2_rn(v.z, v.w);
    *(uint2*)(g_X + (size_t)n * K2 + q * 4) = p.u;
}

// ---------------- K2: W2 transposed [j][k] -> fp16 ----------------
__global__ void k_convw(const float* __restrict__ Ws, const float* __restrict__ Wn) {
    int i = blockIdx.x * blockDim.x + threadIdx.x;
    if (i >= D * K2) return;
    int j = i >> 8, k = i & 255;
    float w = (k < D) ? Ws[k * D + j] : Wn[(k - D) * D + j];
    g_Wt[j * K2 + k] = __float2half_rn(w);
}

// ---------------- K3: padded in-edge lists, 4 edges/thread ----------------
__global__ void k_scatter(const int* __restrict__ src, const int* __restrict__ dst, int E) {
    int q = blockIdx.x * blockDim.x + threadIdx.x;
    int e0 = q * 4;
    if (e0 + 4 <= E) {
        int4 s = *(const int4*)(src + e0);
        int4 d = *(const int4*)(dst + e0);
        int p0 = atomicAdd(&g_cnt[d.x], 1);
        int p1 = atomicAdd(&g_cnt[d.y], 1);
        int p2 = atomicAdd(&g_cnt[d.z], 1);
        int p3 = atomicAdd(&g_cnt[d.w], 1);
        if (p0 < MAXDEG) g_esrc[d.x * MAXDEG + p0] = s.x;
        if (p1 < MAXDEG) g_esrc[d.y * MAXDEG + p1] = s.y;
        if (p2 < MAXDEG) g_esrc[d.z * MAXDEG + p2] = s.z;
        if (p3 < MAXDEG) g_esrc[d.w * MAXDEG + p3] = s.w;
    } else {
        for (int e = e0; e < E; ++e) {
            int v = dst[e];
            int p = atomicAdd(&g_cnt[v], 1);
            if (p < MAXDEG) g_esrc[v * MAXDEG + p] = src[e];
        }
    }
}

// ---------------- K4: pull-mode mean aggregation (fp16 gather, fp32 accum) ----
__global__ void k_agg(int N) {
    int w    = (blockIdx.x * blockDim.x + threadIdx.x) >> 5;
    int lane = threadIdx.x & 31;
    if (w >= N) return;
    int d = g_cnt[w];
    if (d > MAXDEG) d = MAXDEG;
    const int* lst = g_esrc + (size_t)w * MAXDEG;

    float a0 = 0.f, a1 = 0.f, a2 = 0.f, a3 = 0.f;
    int i = 0;
    for (; i + 4 <= d; i += 4) {
        int s0 = __ldg(&lst[i]);
        int s1 = __ldg(&lst[i + 1]);
        int s2 = __ldg(&lst[i + 2]);
        int s3 = __ldg(&lst[i + 3]);
        union { uint2 u; __half2 h[2]; } c0, c1, c2, c3;
        c0.u = *(const uint2*)(g_X + (size_t)s0 * K2 + lane * 4);
        c1.u = *(const uint2*)(g_X + (size_t)s1 * K2 + lane * 4);
        c2.u = *(const uint2*)(g_X + (size_t)s2 * K2 + lane * 4);
        c3.u = *(const uint2*)(g_X + (size_t)s3 * K2 + lane * 4);
        float2 f;
        f = __half22float2(c0.h[0]); a0 += f.x; a1 += f.y;
        f = __half22float2(c0.h[1]); a2 += f.x; a3 += f.y;
        f = __half22float2(c1.h[0]); a0 += f.x; a1 += f.y;
        f = __half22float2(c1.h[1]); a2 += f.x; a3 += f.y;
        f = __half22float2(c2.h[0]); a0 += f.x; a1 += f.y;
        f = __half22float2(c2.h[1]); a2 += f.x; a3 += f.y;
        f = __half22float2(c3.h[0]); a0 += f.x; a1 += f.y;
        f = __half22float2(c3.h[1]); a2 += f.x; a3 += f.y;
    }
    for (; i < d; ++i) {
        int s0 = __ldg(&lst[i]);
        union { uint2 u; __half2 h[2]; } c0;
        c0.u = *(const uint2*)(g_X + (size_t)s0 * K2 + lane * 4);
        float2 f;
        f = __half22float2(c0.h[0]); a0 += f.x; a1 += f.y;
        f = __half22float2(c0.h[1]); a2 += f.x; a3 += f.y;
    }
    float inv = 1.0f / (float)(d > 0 ? d : 1);
    union { __half2 h[2]; uint2 u; } p;
    p.h[0] = __floats2half2_rn(a0 * inv, a1 * inv);
    p.h[1] = __floats2half2_rn(a2 * inv, a3 * inv);
    *(uint2*)(g_X + (size_t)w * K2 + D + lane * 4) = p.u;
}

// ---------------- K5: HMMA GEMM  out = X @ W2t^T + b  (fp16) ----------------
// CTA: M=128 x N=128, K=256 in 4 chunks of 64 (row = 128B, XOR swizzle).
// Warps 4(m) x 2(n): warp tile 32 x 64. Double-buffered cp.async.
#define CHUNK_BYTES 16384            // 128 rows x 128 B
#define BUF_BYTES   32768            // A chunk + B chunk
#define SM_BIAS     (2 * BUF_BYTES)  // 65536
#define SM_TOTAL    (SM_BIAS + D * 4)

__global__ void __launch_bounds__(256, 2)
k_gemm(const float* __restrict__ bias, float* __restrict__ out, int N) {
    extern __shared__ char smem[];
    const uint32_t sbase = smem_u32(smem);
    const int t    = threadIdx.x;
    const int lane = t & 31;
    const int wid  = t >> 5;
    const int m0   = (wid & 3) * 32;
    const int n0w  = (wid >> 2) * 64;
    const int base = blockIdx.x * 128;

    if (t < D) ((float*)(smem + SM_BIAS))[t] = bias[t];

    const int qa = lane >> 3;
    const uint32_t rowA = (lane & 7) + ((qa & 1) << 3);
    const uint32_t kbA  = (qa >> 1) << 4;
    const uint32_t rowB = (lane & 7) + ((qa >> 1) << 3);
    const uint32_t kbB  = (qa & 1) << 4;

    auto load_chunk = [&](int c, int b) {
        uint32_t sb = sbase + b * BUF_BYTES;
        const char* gA = (const char*)(g_X + (size_t)base * K2 + c * 64);
        const char* gB = (const char*)(g_Wt + c * 64);
#pragma unroll
        for (int r = 0; r < 4; ++r) {
            int u   = t + 256 * r;
            int row = u >> 3, kk = u & 7;
            uint32_t so = SWZ((uint32_t)(row * 128 + kk * 16));
            size_t   go = (size_t)row * 512 + kk * 16;      // gmem row stride 512B
            CP16(sb +               so, gA + go);
            CP16(sb + CHUNK_BYTES + so, gB + go);
        }
        CP_COMMIT();
    };

    float acc[2][8][4];
#pragma unroll
    for (int mt = 0; mt < 2; ++mt)
#pragma unroll
        for (int nt = 0; nt < 8; ++nt)
#pragma unroll
            for (int q = 0; q < 4; ++q) acc[mt][nt][q] = 0.f;

    load_chunk(0, 0);

    for (int c = 0; c < 4; ++c) {
        if (c < 3) { load_chunk(c + 1, (c + 1) & 1); CP_WAIT(1); }
        else       { CP_WAIT(0); }
        __syncthreads();

        const uint32_t bA = sbase + (c & 1) * BUF_BYTES;
        const uint32_t bB = bA + CHUNK_BYTES;
#pragma unroll
        for (int ks = 0; ks < 4; ++ks) {
            uint32_t ah[2][4], bh[4][4];
#pragma unroll
            for (int mt = 0; mt < 2; ++mt) {
                uint32_t off = SWZ((uint32_t)((m0 + mt * 16 + rowA) * 128 + ks * 32 + kbA));
                LDM_X4(ah[mt], bA + off);
            }
#pragma unroll
            for (int nb = 0; nb < 4; ++nb) {
                uint32_t off = SWZ((uint32_t)((n0w + nb * 16 + rowB) * 128 + ks * 32 + kbB));
                LDM_X4(bh[nb], bB + off);
            }
#pragma unroll
            for (int mt = 0; mt < 2; ++mt)
#pragma unroll
                for (int nb = 0; nb < 4; ++nb) {
                    MMA16816(acc[mt][nb * 2],     ah[mt], bh[nb][0], bh[nb][1]);
                    MMA16816(acc[mt][nb * 2 + 1], ah[mt], bh[nb][2], bh[nb][3]);
                }
        }
        __syncthreads();
    }

    const float* sb = (const float*)(smem + SM_BIAS);
#pragma unroll
    for (int mt = 0; mt < 2; ++mt) {
        int row = m0 + mt * 16 + (lane >> 2);
#pragma unroll
        for (int nt = 0; nt < 8; ++nt) {
            int j = n0w + nt * 8 + (lane & 3) * 2;
            float2 bb = make_float2(sb[j], sb[j + 1]);
            int n0 = base + row, n1 = n0 + 8;
            if (n0 < N) {
                float2 v = make_float2(acc[mt][nt][0] + bb.x, acc[mt][nt][1] + bb.y);
                *(float2*)(out + (size_t)n0 * D + j) = v;
            }
            if (n1 < N) {
                float2 v = make_float2(acc[mt][nt][2] + bb.x, acc[mt][nt][3] + bb.y);
                *(float2*)(out + (size_t)n1 * D + j) = v;
            }
        }
    }
}

// ---------------- launch ----------------
extern "C" void kernel_launch(void* const* d_in, const int* in_sizes, int n_in,
                              void* d_out, int out_size) {
    const float* feat = (const float*)d_in[0];
    const int*   src  = (const int*)d_in[1];
    const int*   dst  = (const int*)d_in[2];
    const float* Ws   = (const float*)d_in[3];
    const float* Wn   = (const float*)d_in[4];
    const float* b    = (const float*)d_in[5];
    float*       out  = (float*)d_out;

    const int N = in_sizes[0] / D;
    const int E = in_sizes[1];

    k_convx  <<<(N * 32 + 255) / 256, 256>>>(feat, N);   // also zeroes g_cnt
    k_convw  <<<(D * K2 + 255) / 256, 256>>>(Ws, Wn);
    k_scatter<<<((E + 3) / 4 + 255) / 256, 256>>>(src, dst, E);
    k_agg    <<<(N + 7) / 8, 256>>>(N);

    const int grid = (N + 127) / 128;
    cudaFuncSetAttribute(k_gemm, cudaFuncAttributeMaxDynamicSharedMemorySize, SM_TOTAL);
    k_gemm<<<grid, 256, SM_TOTAL>>>(b, out, N);
}

// round 5
// speedup vs baseline: 2.3622x; 1.0101x over previous
#include <cuda_runtime.h>
#include <cuda_fp16.h>
#include <cstdint>

#define D 128
#define K2 256
#define NPAD 50048
#define MAXDEG 96

// ---------------- static device scratch ----------------
__device__ int    g_cnt[NPAD];
__device__ int    g_esrc[NPAD * MAXDEG];
__device__ __half g_X[(size_t)NPAD * K2];    // [n][256]: cols 0-127 feat, 128-255 h
__device__ __half g_Wt[D * K2];              // B operand [j][k] (W2 transposed)

#define SWZ(o) ((o) ^ (((o) >> 3) & 0x70))

__device__ __forceinline__ uint32_t smem_u32(const void* p) {
    uint32_t a;
    asm("{ .reg .u64 t; cvta.to.shared.u64 t, %1; cvt.u32.u64 %0, t; }" : "=r"(a) : "l"(p));
    return a;
}
#define LDM_X4(r, a) \
    asm volatile("ldmatrix.sync.aligned.m8n8.x4.shared.b16 {%0,%1,%2,%3}, [%4];" \
        : "=r"((r)[0]), "=r"((r)[1]), "=r"((r)[2]), "=r"((r)[3]) : "r"(a))
#define MMA16816(c, a, b0, b1) \
    asm volatile("mma.sync.aligned.m16n8k16.row.col.f32.f16.f16.f32 " \
        "{%0,%1,%2,%3},{%4,%5,%6,%7},{%8,%9},{%0,%1,%2,%3};" \
        : "+f"((c)[0]), "+f"((c)[1]), "+f"((c)[2]), "+f"((c)[3]) \
        : "r"((a)[0]), "r"((a)[1]), "r"((a)[2]), "r"((a)[3]), "r"(b0), "r"(b1))
#define CP16(s, g) \
    asm volatile("cp.async.cg.shared.global [%0], [%1], 16;" :: "r"(s), "l"(g))
#define CP_COMMIT()  asm volatile("cp.async.commit_group;" ::: "memory")
#define CP_WAIT(n)   asm volatile("cp.async.wait_group %0;" :: "n"(n) : "memory")

// ---------------- K1: features -> fp16, W2^T -> fp16, zero g_cnt ------------
__global__ void k_conv(const float* __restrict__ feat,
                       const float* __restrict__ Ws,
                       const float* __restrict__ Wn, int N) {
    int i = blockIdx.x * blockDim.x + threadIdx.x;
    if (i < N) g_cnt[i] = 0;
    if (i < D * K2) {                       // W2 transposed [j][k]
        int j = i >> 8, k = i & 255;
        float w = (k < D) ? Ws[k * D + j] : Wn[(k - D) * D + j];
        g_Wt[j * K2 + k] = __float2half_rn(w);
    }
    if (i >= N * 32) return;
    int n = i >> 5, q = i & 31;
    float4 v = ((const float4*)feat)[i];
    union { __half2 h[2]; uint2 u; } p;
    p.h[0] = __floats2half2_rn(v.x, v.y);
    p.h[1] = __floats2half2_rn(v.z, v.w);
    *(uint2*)(g_X + (size_t)n * K2 + q * 4) = p.u;
}

// ---------------- K2: padded in-edge lists, 4 edges/thread ----------------
__global__ void k_scatter(const int* __restrict__ src, const int* __restrict__ dst, int E) {
    int q = blockIdx.x * blockDim.x + threadIdx.x;
    int e0 = q * 4;
    if (e0 + 4 <= E) {
        int4 s = *(const int4*)(src + e0);
        int4 d = *(const int4*)(dst + e0);
        int p0 = atomicAdd(&g_cnt[d.x], 1);
        int p1 = atomicAdd(&g_cnt[d.y], 1);
        int p2 = atomicAdd(&g_cnt[d.z], 1);
        int p3 = atomicAdd(&g_cnt[d.w], 1);
        if (p0 < MAXDEG) g_esrc[d.x * MAXDEG + p0] = s.x;
        if (p1 < MAXDEG) g_esrc[d.y * MAXDEG + p1] = s.y;
        if (p2 < MAXDEG) g_esrc[d.z * MAXDEG + p2] = s.z;
        if (p3 < MAXDEG) g_esrc[d.w * MAXDEG + p3] = s.w;
    } else {
        for (int e = e0; e < E; ++e) {
            int v = dst[e];
            int p = atomicAdd(&g_cnt[v], 1);
            if (p < MAXDEG) g_esrc[v * MAXDEG + p] = src[e];
        }
    }
}

// ---------------- K3: mean aggregation, half-warp/edge, HADD2 accum ----------
// Warp per node. Lane = (half, l): half-warp `half` takes edges j%2==half,
// lane group l (0..15) owns halves [8l, 8l+8) via one uint4 (16B) load/edge.
// fp16 accumulate <=16 edges (<=8 adds per reg), fold to fp32, shfl-combine.
__global__ void k_agg(int N) {
    int gw   = (blockIdx.x * blockDim.x + threadIdx.x) >> 5;
    int lane = threadIdx.x & 31;
    if (gw >= N) return;
    const int half = lane >> 4;
    const int l    = lane & 15;
    int d = g_cnt[gw];
    if (d > MAXDEG) d = MAXDEG;
    const int* lst = g_esrc + (size_t)gw * MAXDEG;
    const __half2* rowbase = (const __half2*)(g_X) + l * 4;   // +s*128 half2s

    float2 f0 = {0.f,0.f}, f1 = {0.f,0.f}, f2 = {0.f,0.f}, f3 = {0.f,0.f};
    int i = 0;
    while (i < d) {
        int chunk = d - i; if (chunk > 16) chunk = 16;
        __half2 h0 = __float2half2_rn(0.f), h1 = h0, h2 = h0, h3 = h0;
        for (int j = half; j < chunk; j += 2) {
            int s = __ldg(&lst[i + j]);
            union { uint4 u; __half2 h[4]; } v;
            v.u = *(const uint4*)(rowbase + (size_t)s * 128);
            h0 = __hadd2(h0, v.h[0]);
            h1 = __hadd2(h1, v.h[1]);
            h2 = __hadd2(h2, v.h[2]);
            h3 = __hadd2(h3, v.h[3]);
        }
        float2 t;
        t = __half22float2(h0); f0.x += t.x; f0.y += t.y;
        t = __half22float2(h1); f1.x += t.x; f1.y += t.y;
        t = __half22float2(h2); f2.x += t.x; f2.y += t.y;
        t = __half22float2(h3); f3.x += t.x; f3.y += t.y;
        i += chunk;
    }
    // combine the two half-warps (same elems, disjoint edge subsets)
    f0.x += __shfl_xor_sync(0xffffffffu, f0.x, 16);
    f0.y += __shfl_xor_sync(0xffffffffu, f0.y, 16);
    f1.x += __shfl_xor_sync(0xffffffffu, f1.x, 16);
    f1.y += __shfl_xor_sync(0xffffffffu, f1.y, 16);
    f2.x += __shfl_xor_sync(0xffffffffu, f2.x, 16);
    f2.y += __shfl_xor_sync(0xffffffffu, f2.y, 16);
    f3.x += __shfl_xor_sync(0xffffffffu, f3.x, 16);
    f3.y += __shfl_xor_sync(0xffffffffu, f3.y, 16);

    if (half == 0) {
        float inv = 1.0f / (float)(d > 0 ? d : 1);
        union { __half2 h[4]; uint4 u; } p;
        p.h[0] = __floats2half2_rn(f0.x * inv, f0.y * inv);
        p.h[1] = __floats2half2_rn(f1.x * inv, f1.y * inv);
        p.h[2] = __floats2half2_rn(f2.x * inv, f2.y * inv);
        p.h[3] = __floats2half2_rn(f3.x * inv, f3.y * inv);
        *(uint4*)(g_X + (size_t)gw * K2 + D + l * 8) = p.u;
    }
}

// ---------------- K4: HMMA GEMM  out = X @ W2t^T + b  (fp16) ----------------
#define CHUNK_BYTES 16384            // 128 rows x 128 B
#define BUF_BYTES   32768            // A chunk + B chunk
#define SM_BIAS     (2 * BUF_BYTES)  // 65536
#define SM_TOTAL    (SM_BIAS + D * 4)

__global__ void __launch_bounds__(256, 2)
k_gemm(const float* __restrict__ bias, float* __restrict__ out, int N) {
    extern __shared__ char smem[];
    const uint32_t sbase = smem_u32(smem);
    const int t    = threadIdx.x;
    const int lane = t & 31;
    const int wid  = t >> 5;
    const int m0   = (wid & 3) * 32;
    const int n0w  = (wid >> 2) * 64;
    const int base = blockIdx.x * 128;

    if (t < D) ((float*)(smem + SM_BIAS))[t] = bias[t];

    const int qa = lane >> 3;
    const uint32_t rowA = (lane & 7) + ((qa & 1) << 3);
    const uint32_t kbA  = (qa >> 1) << 4;
    const uint32_t rowB = (lane & 7) + ((qa >> 1) << 3);
    const uint32_t kbB  = (qa & 1) << 4;

    auto load_chunk = [&](int c, int b) {
        uint32_t sb = sbase + b * BUF_BYTES;
        const char* gA = (const char*)(g_X + (size_t)base * K2 + c * 64);
        const char* gB = (const char*)(g_Wt + c * 64);
#pragma unroll
        for (int r = 0; r < 4; ++r) {
            int u   = t + 256 * r;
            int row = u >> 3, kk = u & 7;
            uint32_t so = SWZ((uint32_t)(row * 128 + kk * 16));
            size_t   go = (size_t)row * 512 + kk * 16;
            CP16(sb +               so, gA + go);
            CP16(sb + CHUNK_BYTES + so, gB + go);
        }
        CP_COMMIT();
    };

    float acc[2][8][4];
#pragma unroll
    for (int mt = 0; mt < 2; ++mt)
#pragma unroll
        for (int nt = 0; nt < 8; ++nt)
#pragma unroll
            for (int q = 0; q < 4; ++q) acc[mt][nt][q] = 0.f;

    load_chunk(0, 0);

    for (int c = 0; c < 4; ++c) {
        if (c < 3) { load_chunk(c + 1, (c + 1) & 1); CP_WAIT(1); }
        else       { CP_WAIT(0); }
        __syncthreads();

        const uint32_t bA = sbase + (c & 1) * BUF_BYTES;
        const uint32_t bB = bA + CHUNK_BYTES;
#pragma unroll
        for (int ks = 0; ks < 4; ++ks) {
            uint32_t ah[2][4], bh[4][4];
#pragma unroll
            for (int mt = 0; mt < 2; ++mt) {
                uint32_t off = SWZ((uint32_t)((m0 + mt * 16 + rowA) * 128 + ks * 32 + kbA));
                LDM_X4(ah[mt], bA + off);
            }
#pragma unroll
            for (int nb = 0; nb < 4; ++nb) {
                uint32_t off = SWZ((uint32_t)((n0w + nb * 16 + rowB) * 128 + ks * 32 + kbB));
                LDM_X4(bh[nb], bB + off);
            }
#pragma unroll
            for (int mt = 0; mt < 2; ++mt)
#pragma unroll
                for (int nb = 0; nb < 4; ++nb) {
                    MMA16816(acc[mt][nb * 2],     ah[mt], bh[nb][0], bh[nb][1]);
                    MMA16816(acc[mt][nb * 2 + 1], ah[mt], bh[nb][2], bh[nb][3]);
                }
        }
        __syncthreads();
    }

    const float* sb = (const float*)(smem + SM_BIAS);
#pragma unroll
    for (int mt = 0; mt < 2; ++mt) {
        int row = m0 + mt * 16 + (lane >> 2);
#pragma unroll
        for (int nt = 0; nt < 8; ++nt) {
            int j = n0w + nt * 8 + (lane & 3) * 2;
            float2 bb = make_float2(sb[j], sb[j + 1]);
            int n0 = base + row, n1 = n0 + 8;
            if (n0 < N) {
                float2 v = make_float2(acc[mt][nt][0] + bb.x, acc[mt][nt][1] + bb.y);
                *(float2*)(out + (size_t)n0 * D + j) = v;
            }
            if (n1 < N) {
                float2 v = make_float2(acc[mt][nt][2] + bb.x, acc[mt][nt][3] + bb.y);
                *(float2*)(out + (size_t)n1 * D + j) = v;
            }
        }
    }
}

// ---------------- launch ----------------
extern "C" void kernel_launch(void* const* d_in, const int* in_sizes, int n_in,
                              void* d_out, int out_size) {
    const float* feat = (const float*)d_in[0];
    const int*   src  = (const int*)d_in[1];
    const int*   dst  = (const int*)d_in[2];
    const float* Ws   = (const float*)d_in[3];
    const float* Wn   = (const float*)d_in[4];
    const float* b    = (const float*)d_in[5];
    float*       out  = (float*)d_out;

    const int N = in_sizes[0] / D;
    const int E = in_sizes[1];

    k_conv   <<<(N * 32 + 255) / 256, 256>>>(feat, Ws, Wn, N);
    k_scatter<<<((E + 3) / 4 + 255) / 256, 256>>>(src, dst, E);
    k_agg    <<<(N + 7) / 8, 256>>>(N);

    const int grid = (N + 127) / 128;
    cudaFuncSetAttribute(k_gemm, cudaFuncAttributeMaxDynamicSharedMemorySize, SM_TOTAL);
    k_gemm<<<grid, 256, SM_TOTAL>>>(b, out, N);
}